// round 6
// baseline (speedup 1.0000x reference)
#include <cuda_runtime.h>
#include <cstdint>

#define NTH 512
#define WLS 132   // padded row stride (floats) for the W_lin staging tile: conflict-free transpose

static __device__ __forceinline__ float sigf(float v) {
    return __fdividef(1.0f, 1.0f + __expf(-v));
}
static __device__ __forceinline__ float tanh_acc(float v) {
    // exact identity tanh(x) = 1 - 2/(e^{2x}+1); only __expf rounding (~2^-22)
    return 1.0f - __fdividef(2.0f, __expf(2.0f * v) + 1.0f);
}

// NOTE: macro params must not collide with float4 field names (.x/.y/.z/.w)
#define FMA4(D, S, V)                    \
    (D).x = fmaf((S), (V).x, (D).x);     \
    (D).y = fmaf((S), (V).y, (D).y);     \
    (D).z = fmaf((S), (V).z, (D).z);     \
    (D).w = fmaf((S), (V).w, (D).w);

__global__ void __launch_bounds__(NTH, 1)
lstm_fused_kernel(const float* __restrict__ x,      // [8192,128,32]
                  const float* __restrict__ W_ih,   // [256,32]
                  const float* __restrict__ W_hh,   // [256,64]
                  const float* __restrict__ b_ih,   // [256]
                  const float* __restrict__ b_hh,   // [256]
                  const float* __restrict__ W_lin,  // [100,8192]
                  const float* __restrict__ b_lin,  // [100]
                  float* __restrict__ out)          // [8192,100]
{
    constexpr int T = 128, F = 32, H = 64;
    extern __shared__ float smem[];
    float4* s_wih  = (float4*)smem;              // [F][2][32]   : 2048 float4
    float4* s_whh  = (float4*)(smem + 8192);     // [H][2][32]   : 4096 float4
    float4* s_bias = (float4*)(smem + 24576);    // [2][32]      : 64 float4
    float*  s_wlin = smem + 24832;               // [64][WLS]

    const int tid  = threadIdx.x;
    const int lane = tid & 31;
    const int warp = tid >> 5;

    // ---- one-time staging: permuted weights so gate g = lane + 32*(4m+c) ----
    for (int u = tid; u < F * 64; u += NTH) {
        int f = u >> 6, m = (u >> 5) & 1, l = u & 31;
        float4 v;
        v.x = W_ih[(l + 32 * (4 * m + 0)) * F + f];
        v.y = W_ih[(l + 32 * (4 * m + 1)) * F + f];
        v.z = W_ih[(l + 32 * (4 * m + 2)) * F + f];
        v.w = W_ih[(l + 32 * (4 * m + 3)) * F + f];
        s_wih[u] = v;
    }
    for (int u = tid; u < H * 64; u += NTH) {
        int j = u >> 6, m = (u >> 5) & 1, l = u & 31;
        float4 v;
        v.x = W_hh[(l + 32 * (4 * m + 0)) * H + j];
        v.y = W_hh[(l + 32 * (4 * m + 1)) * H + j];
        v.z = W_hh[(l + 32 * (4 * m + 2)) * H + j];
        v.w = W_hh[(l + 32 * (4 * m + 3)) * H + j];
        s_whh[u] = v;
    }
    if (tid < 64) {
        int m = (tid >> 5) & 1, l = tid & 31;
        float4 v;
        v.x = b_ih[l + 32 * (4 * m + 0)] + b_hh[l + 32 * (4 * m + 0)];
        v.y = b_ih[l + 32 * (4 * m + 1)] + b_hh[l + 32 * (4 * m + 1)];
        v.z = b_ih[l + 32 * (4 * m + 2)] + b_hh[l + 32 * (4 * m + 2)];
        v.w = b_ih[l + 32 * (4 * m + 3)] + b_hh[l + 32 * (4 * m + 3)];
        s_bias[tid] = v;
    }
    // zero the padding columns 100..131 once (lanes 25..31 read them harmlessly)
    for (int u = tid; u < 64 * 32; u += NTH) {
        int j = u >> 5, c = u & 31;
        s_wlin[j * WLS + 100 + c] = 0.0f;
    }

    const int row0 = blockIdx.x * 32 + warp * 2;
    const int row1 = row0 + 1;

    float h_lo0 = 0.f, h_hi0 = 0.f, c_lo0 = 0.f, c_hi0 = 0.f;
    float h_lo1 = 0.f, h_hi1 = 0.f, c_lo1 = 0.f, c_hi1 = 0.f;

    float4 lg0 = make_float4(0.f, 0.f, 0.f, 0.f);
    float4 lg1 = lg0;
    if (lane < 25) {
        lg0 = *(const float4*)(b_lin + 4 * lane);
        lg1 = lg0;
    }

    const float* xp0 = x + (size_t)row0 * T * F + lane;
    const float* xp1 = x + (size_t)row1 * T * F + lane;
    float xn0 = xp0[0];
    float xn1 = xp1[0];

    __syncthreads();

    for (int t = 0; t < T; ++t) {
        // stage W_lin slice for this t: s_wlin[j][a] = W_lin[a][t*64+j]
        {
            const float* wl = W_lin + t * H;
            for (int u = tid; u < 1600; u += NTH) {
                int j  = u & 63;
                int a0 = (u >> 6) << 2;
                float4 v;
                v.x = wl[(a0 + 0) * 8192 + j];
                v.y = wl[(a0 + 1) * 8192 + j];
                v.z = wl[(a0 + 2) * 8192 + j];
                v.w = wl[(a0 + 3) * 8192 + j];
                *(float4*)(s_wlin + j * WLS + a0) = v;
            }
        }

        float xv0 = xn0, xv1 = xn1;
        int tn = (t + 1 < T) ? (t + 1) : t;
        xn0 = xp0[tn * F];
        xn1 = xp1[tn * F];

        float4 a00 = s_bias[lane], a01 = s_bias[32 + lane];
        float4 a10 = a00, a11 = a01;

        #pragma unroll 8
        for (int f = 0; f < F; ++f) {
            float4 w0 = s_wih[f * 64 + lane];
            float4 w1 = s_wih[f * 64 + 32 + lane];
            float v0 = __shfl_sync(0xffffffffu, xv0, f);
            float v1 = __shfl_sync(0xffffffffu, xv1, f);
            FMA4(a00, v0, w0); FMA4(a01, v0, w1);
            FMA4(a10, v1, w0); FMA4(a11, v1, w1);
        }
        #pragma unroll 8
        for (int j = 0; j < 32; ++j) {
            float4 w0 = s_whh[j * 64 + lane];
            float4 w1 = s_whh[j * 64 + 32 + lane];
            float v0 = __shfl_sync(0xffffffffu, h_lo0, j);
            float v1 = __shfl_sync(0xffffffffu, h_lo1, j);
            FMA4(a00, v0, w0); FMA4(a01, v0, w1);
            FMA4(a10, v1, w0); FMA4(a11, v1, w1);
            float4 W0 = s_whh[(j + 32) * 64 + lane];
            float4 W1 = s_whh[(j + 32) * 64 + 32 + lane];
            float u0 = __shfl_sync(0xffffffffu, h_hi0, j);
            float u1 = __shfl_sync(0xffffffffu, h_hi1, j);
            FMA4(a00, u0, W0); FMA4(a01, u0, W1);
            FMA4(a10, u1, W0); FMA4(a11, u1, W1);
        }

        // elementwise LSTM update (gate quadruple is lane-local by construction)
        {
            float ii = sigf(a00.x), ih = sigf(a00.y);
            float ff = sigf(a00.z), fh = sigf(a00.w);
            float gg = tanh_acc(a01.x), gh = tanh_acc(a01.y);
            float oo = sigf(a01.z), oh = sigf(a01.w);
            c_lo0 = ff * c_lo0 + ii * gg;
            c_hi0 = fh * c_hi0 + ih * gh;
            h_lo0 = oo * tanh_acc(c_lo0);
            h_hi0 = oh * tanh_acc(c_hi0);
        }
        {
            float ii = sigf(a10.x), ih = sigf(a10.y);
            float ff = sigf(a10.z), fh = sigf(a10.w);
            float gg = tanh_acc(a11.x), gh = tanh_acc(a11.y);
            float oo = sigf(a11.z), oh = sigf(a11.w);
            c_lo1 = ff * c_lo1 + ii * gg;
            c_hi1 = fh * c_hi1 + ih * gh;
            h_lo1 = oo * tanh_acc(c_lo1);
            h_hi1 = oh * tanh_acc(c_hi1);
        }

        __syncthreads();  // s_wlin staged

        // online logits accumulation: lg[a] += h_t[j] * W_lin[a, t*64+j]
        #pragma unroll 8
        for (int j = 0; j < 32; ++j) {
            float4 wl = *(const float4*)(s_wlin + j * WLS + 4 * lane);
            float4 wh = *(const float4*)(s_wlin + (j + 32) * WLS + 4 * lane);
            float v0 = __shfl_sync(0xffffffffu, h_lo0, j);
            float v1 = __shfl_sync(0xffffffffu, h_lo1, j);
            float u0 = __shfl_sync(0xffffffffu, h_hi0, j);
            float u1 = __shfl_sync(0xffffffffu, h_hi1, j);
            FMA4(lg0, v0, wl); FMA4(lg0, u0, wh);
            FMA4(lg1, v1, wl); FMA4(lg1, u1, wh);
        }

        __syncthreads();  // protect s_wlin before next overwrite
    }

    // ---- softmax over 100 assets, distributed across lanes 0..24 (4 each) ----
    const float NEG_INF = __int_as_float(0xff800000);
    float m0 = (lane < 25) ? fmaxf(fmaxf(lg0.x, lg0.y), fmaxf(lg0.z, lg0.w)) : NEG_INF;
    float m1 = (lane < 25) ? fmaxf(fmaxf(lg1.x, lg1.y), fmaxf(lg1.z, lg1.w)) : NEG_INF;
    #pragma unroll
    for (int off = 16; off; off >>= 1) {
        m0 = fmaxf(m0, __shfl_xor_sync(0xffffffffu, m0, off));
        m1 = fmaxf(m1, __shfl_xor_sync(0xffffffffu, m1, off));
    }
    float4 e0 = make_float4(0.f, 0.f, 0.f, 0.f), e1 = e0;
    float s0 = 0.f, s1 = 0.f;
    if (lane < 25) {
        e0.x = __expf(lg0.x - m0); e0.y = __expf(lg0.y - m0);
        e0.z = __expf(lg0.z - m0); e0.w = __expf(lg0.w - m0);
        e1.x = __expf(lg1.x - m1); e1.y = __expf(lg1.y - m1);
        e1.z = __expf(lg1.z - m1); e1.w = __expf(lg1.w - m1);
        s0 = (e0.x + e0.y) + (e0.z + e0.w);
        s1 = (e1.x + e1.y) + (e1.z + e1.w);
    }
    #pragma unroll
    for (int off = 16; off; off >>= 1) {
        s0 += __shfl_xor_sync(0xffffffffu, s0, off);
        s1 += __shfl_xor_sync(0xffffffffu, s1, off);
    }
    if (lane < 25) {
        float r0 = __fdividef(1.0f, s0);
        float r1 = __fdividef(1.0f, s1);
        float4 o0 = make_float4(e0.x * r0, e0.y * r0, e0.z * r0, e0.w * r0);
        float4 o1 = make_float4(e1.x * r1, e1.y * r1, e1.z * r1, e1.w * r1);
        *(float4*)(out + (size_t)row0 * 100 + 4 * lane) = o0;
        *(float4*)(out + (size_t)row1 * 100 + 4 * lane) = o1;
    }
}

extern "C" void kernel_launch(void* const* d_in, const int* in_sizes, int n_in,
                              void* d_out, int out_size) {
    const float* x     = (const float*)d_in[0];
    const float* W_ih  = (const float*)d_in[1];
    const float* W_hh  = (const float*)d_in[2];
    const float* b_ih  = (const float*)d_in[3];
    const float* b_hh  = (const float*)d_in[4];
    const float* W_lin = (const float*)d_in[5];
    const float* b_lin = (const float*)d_in[6];
    float* out = (float*)d_out;

    const int smem_bytes = (8192 + 16384 + 256 + 64 * WLS) * 4;  // 133120
    cudaFuncSetAttribute(lstm_fused_kernel,
                         cudaFuncAttributeMaxDynamicSharedMemorySize, smem_bytes);
    lstm_fused_kernel<<<256, NTH, smem_bytes>>>(x, W_ih, W_hh, b_ih, b_hh,
                                                W_lin, b_lin, out);
}

// round 7
// speedup vs baseline: 1.5402x; 1.5402x over previous
#include <cuda_runtime.h>
#include <cstdint>

#define NTH 256
#define WLS 128
typedef unsigned long long u64;

// 4 MB transposed+padded W_lin: g_wlinT[k][a] = W_lin[a][k], a padded 100->128 with zeros
__device__ float g_wlinT[8192 * 128];

__global__ void __launch_bounds__(256)
transpose_wlin_kernel(const float* __restrict__ W_lin) {
    int idx = blockIdx.x * 256 + threadIdx.x;   // 0 .. 8192*128-1
    int a = idx & 127;
    int k = idx >> 7;
    g_wlinT[idx] = (a < 100) ? W_lin[a * 8192 + k] : 0.0f;
}

static __device__ __forceinline__ float sigf(float v) {
    return __fdividef(1.0f, 1.0f + __expf(-v));
}
static __device__ __forceinline__ float tanh_acc(float v) {
    return 1.0f - __fdividef(2.0f, __expf(2.0f * v) + 1.0f);
}
static __device__ __forceinline__ u64 pack2(float s) {
    u64 r; asm("mov.b64 %0, {%1, %1};" : "=l"(r) : "f"(s)); return r;
}
static __device__ __forceinline__ u64 pack2f(float a, float b) {
    u64 r; asm("mov.b64 %0, {%1, %2};" : "=l"(r) : "f"(a), "f"(b)); return r;
}
static __device__ __forceinline__ float2 unpk(u64 v) {
    float2 f; asm("mov.b64 {%0, %1}, %2;" : "=f"(f.x), "=f"(f.y) : "l"(v)); return f;
}
static __device__ __forceinline__ void fma2(u64 &d, u64 w, u64 s) {
    asm("fma.rn.f32x2 %0, %1, %2, %0;" : "+l"(d) : "l"(w), "l"(s));
}
static __device__ __forceinline__ void cp16(uint32_t dst, const void* src) {
    asm volatile("cp.async.cg.shared.global [%0], [%1], 16;" :: "r"(dst), "l"(src));
}

__global__ void __launch_bounds__(NTH, 1)
lstm_fused_kernel(const float* __restrict__ x,      // [8192,128,32]
                  const float* __restrict__ W_ih,   // [256,32]
                  const float* __restrict__ W_hh,   // [256,64]
                  const float* __restrict__ b_ih,   // [256]
                  const float* __restrict__ b_hh,   // [256]
                  const float* __restrict__ b_lin,  // [100]
                  float* __restrict__ out)          // [8192,100]
{
    constexpr int T = 128, F = 32, H = 64;
    extern __shared__ float smem[];
    float4* s_wih  = (float4*)smem;              // [F][2][32]   : 2048 float4
    float4* s_whh  = (float4*)(smem + 8192);     // [H][2][32]   : 4096 float4
    float4* s_bias = (float4*)(smem + 24576);    // [2][32]      : 64 float4
    float*  s_wlin = smem + 24832;               // [64][WLS=128]: 8192 floats

    const int tid  = threadIdx.x;
    const int lane = tid & 31;
    const int warp = tid >> 5;

    // ---- one-time staging: permuted weights so gate g = lane + 32*(4m+c) ----
    for (int u = tid; u < F * 64; u += NTH) {
        int f = u >> 6, m = (u >> 5) & 1, l = u & 31;
        float4 v;
        v.x = W_ih[(l + 32 * (4 * m + 0)) * F + f];
        v.y = W_ih[(l + 32 * (4 * m + 1)) * F + f];
        v.z = W_ih[(l + 32 * (4 * m + 2)) * F + f];
        v.w = W_ih[(l + 32 * (4 * m + 3)) * F + f];
        s_wih[u] = v;
    }
    for (int u = tid; u < H * 64; u += NTH) {
        int j = u >> 6, m = (u >> 5) & 1, l = u & 31;
        float4 v;
        v.x = W_hh[(l + 32 * (4 * m + 0)) * H + j];
        v.y = W_hh[(l + 32 * (4 * m + 1)) * H + j];
        v.z = W_hh[(l + 32 * (4 * m + 2)) * H + j];
        v.w = W_hh[(l + 32 * (4 * m + 3)) * H + j];
        s_whh[u] = v;
    }
    if (tid < 64) {
        int m = (tid >> 5) & 1, l = tid & 31;
        float4 v;
        v.x = b_ih[l + 32 * (4 * m + 0)] + b_hh[l + 32 * (4 * m + 0)];
        v.y = b_ih[l + 32 * (4 * m + 1)] + b_hh[l + 32 * (4 * m + 1)];
        v.z = b_ih[l + 32 * (4 * m + 2)] + b_hh[l + 32 * (4 * m + 2)];
        v.w = b_ih[l + 32 * (4 * m + 3)] + b_hh[l + 32 * (4 * m + 3)];
        s_bias[tid] = v;
    }

    // 4 rows per warp
    const int row0 = blockIdx.x * 32 + warp * 4;

    float h_lo[4], h_hi[4], c_lo[4], c_hi[4], xv[4], xn[4];
    const float* xp[4];
    u64 lgA[4], lgB[4];

    u64 blA = 0, blB = 0;
    if (lane < 25) {
        float4 b = *(const float4*)(b_lin + 4 * lane);
        blA = pack2f(b.x, b.y);
        blB = pack2f(b.z, b.w);
    }
    #pragma unroll
    for (int r = 0; r < 4; ++r) {
        h_lo[r] = h_hi[r] = c_lo[r] = c_hi[r] = 0.f;
        lgA[r] = blA; lgB[r] = blB;
        xp[r] = x + (size_t)(row0 + r) * T * F + lane;
        xn[r] = xp[r][0];
    }

    const uint32_t wlin_smem = (uint32_t)__cvta_generic_to_shared(s_wlin);

    __syncthreads();

    for (int t = 0; t < T; ++t) {
        // issue staging of this step's W_lin slice: linear 32KB copy (8x 16B/thread)
        {
            const char* src = (const char*)(g_wlinT + t * 8192) + tid * 16;
            uint32_t dst = wlin_smem + tid * 16;
            #pragma unroll
            for (int k = 0; k < 8; ++k)
                cp16(dst + k * 4096, src + k * 4096);
            asm volatile("cp.async.commit_group;" ::: "memory");
        }

        #pragma unroll
        for (int r = 0; r < 4; ++r) xv[r] = xn[r];
        int tn = (t + 1 < T) ? (t + 1) : t;
        #pragma unroll
        for (int r = 0; r < 4; ++r) xn[r] = xp[r][tn * F];

        // gate accumulators (packed pairs): A0=(i_lo,i_hi) A1=(f_lo,f_hi) B0=(g_lo,g_hi) B1=(o_lo,o_hi)
        u64 aA0[4], aA1[4], aB0[4], aB1[4];
        {
            ulonglong2 bb0 = ((const ulonglong2*)s_bias)[lane];
            ulonglong2 bb1 = ((const ulonglong2*)s_bias)[32 + lane];
            #pragma unroll
            for (int r = 0; r < 4; ++r) {
                aA0[r] = bb0.x; aA1[r] = bb0.y;
                aB0[r] = bb1.x; aB1[r] = bb1.y;
            }
        }

        #pragma unroll 8
        for (int f = 0; f < F; ++f) {
            ulonglong2 w0 = *(const ulonglong2*)(s_wih + f * 64 + lane);
            ulonglong2 w1 = *(const ulonglong2*)(s_wih + f * 64 + 32 + lane);
            #pragma unroll
            for (int r = 0; r < 4; ++r) {
                u64 s2 = pack2(__shfl_sync(0xffffffffu, xv[r], f));
                fma2(aA0[r], w0.x, s2); fma2(aA1[r], w0.y, s2);
                fma2(aB0[r], w1.x, s2); fma2(aB1[r], w1.y, s2);
            }
        }
        #pragma unroll 4
        for (int j = 0; j < 32; ++j) {
            ulonglong2 w0 = *(const ulonglong2*)(s_whh + j * 64 + lane);
            ulonglong2 w1 = *(const ulonglong2*)(s_whh + j * 64 + 32 + lane);
            ulonglong2 W0 = *(const ulonglong2*)(s_whh + (j + 32) * 64 + lane);
            ulonglong2 W1 = *(const ulonglong2*)(s_whh + (j + 32) * 64 + 32 + lane);
            #pragma unroll
            for (int r = 0; r < 4; ++r) {
                u64 s2 = pack2(__shfl_sync(0xffffffffu, h_lo[r], j));
                fma2(aA0[r], w0.x, s2); fma2(aA1[r], w0.y, s2);
                fma2(aB0[r], w1.x, s2); fma2(aB1[r], w1.y, s2);
                u64 u2 = pack2(__shfl_sync(0xffffffffu, h_hi[r], j));
                fma2(aA0[r], W0.x, u2); fma2(aA1[r], W0.y, u2);
                fma2(aB0[r], W1.x, u2); fma2(aB1[r], W1.y, u2);
            }
        }

        // elementwise LSTM update
        #pragma unroll
        for (int r = 0; r < 4; ++r) {
            float2 iv = unpk(aA0[r]);
            float2 fv = unpk(aA1[r]);
            float2 gv = unpk(aB0[r]);
            float2 ov = unpk(aB1[r]);
            c_lo[r] = sigf(fv.x) * c_lo[r] + sigf(iv.x) * tanh_acc(gv.x);
            c_hi[r] = sigf(fv.y) * c_hi[r] + sigf(iv.y) * tanh_acc(gv.y);
            h_lo[r] = sigf(ov.x) * tanh_acc(c_lo[r]);
            h_hi[r] = sigf(ov.y) * tanh_acc(c_hi[r]);
        }

        asm volatile("cp.async.wait_group 0;" ::: "memory");
        __syncthreads();  // s_wlin staged

        // online logits accumulation: lg[a] += h_t[j] * W_lin[a, t*64+j]
        #pragma unroll 4
        for (int j = 0; j < 32; ++j) {
            ulonglong2 wl = *(const ulonglong2*)(s_wlin + j * WLS + 4 * lane);
            ulonglong2 wh = *(const ulonglong2*)(s_wlin + (j + 32) * WLS + 4 * lane);
            #pragma unroll
            for (int r = 0; r < 4; ++r) {
                u64 v2 = pack2(__shfl_sync(0xffffffffu, h_lo[r], j));
                fma2(lgA[r], wl.x, v2); fma2(lgB[r], wl.y, v2);
                u64 u2 = pack2(__shfl_sync(0xffffffffu, h_hi[r], j));
                fma2(lgA[r], wh.x, u2); fma2(lgB[r], wh.y, u2);
            }
        }

        __syncthreads();  // protect s_wlin before next overwrite
    }

    // ---- softmax over 100 assets, 4 per lane in lanes 0..24 ----
    const float NEG_INF = __int_as_float(0xff800000);
    #pragma unroll
    for (int r = 0; r < 4; ++r) {
        float2 pa = unpk(lgA[r]);
        float2 pb = unpk(lgB[r]);
        float m = (lane < 25) ? fmaxf(fmaxf(pa.x, pa.y), fmaxf(pb.x, pb.y)) : NEG_INF;
        #pragma unroll
        for (int off = 16; off; off >>= 1)
            m = fmaxf(m, __shfl_xor_sync(0xffffffffu, m, off));
        float e0 = 0.f, e1 = 0.f, e2 = 0.f, e3 = 0.f, s = 0.f;
        if (lane < 25) {
            e0 = __expf(pa.x - m); e1 = __expf(pa.y - m);
            e2 = __expf(pb.x - m); e3 = __expf(pb.y - m);
            s = (e0 + e1) + (e2 + e3);
        }
        #pragma unroll
        for (int off = 16; off; off >>= 1)
            s += __shfl_xor_sync(0xffffffffu, s, off);
        if (lane < 25) {
            float inv = __fdividef(1.0f, s);
            float4 o = make_float4(e0 * inv, e1 * inv, e2 * inv, e3 * inv);
            *(float4*)(out + (size_t)(row0 + r) * 100 + 4 * lane) = o;
        }
    }
}

extern "C" void kernel_launch(void* const* d_in, const int* in_sizes, int n_in,
                              void* d_out, int out_size) {
    const float* x     = (const float*)d_in[0];
    const float* W_ih  = (const float*)d_in[1];
    const float* W_hh  = (const float*)d_in[2];
    const float* b_ih  = (const float*)d_in[3];
    const float* b_hh  = (const float*)d_in[4];
    const float* W_lin = (const float*)d_in[5];
    const float* b_lin = (const float*)d_in[6];
    float* out = (float*)d_out;

    transpose_wlin_kernel<<<8192 * 128 / 256, 256>>>(W_lin);

    const int smem_bytes = (24832 + 64 * WLS) * 4;  // 132096
    cudaFuncSetAttribute(lstm_fused_kernel,
                         cudaFuncAttributeMaxDynamicSharedMemorySize, smem_bytes);
    lstm_fused_kernel<<<256, NTH, smem_bytes>>>(x, W_ih, W_hh, b_ih, b_hh,
                                                b_lin, out);
}

// round 10
// speedup vs baseline: 1.7144x; 1.1131x over previous
#include <cuda_runtime.h>
#include <cstdint>

#define NTH 256
#define WLS 128
#define R 8
typedef unsigned long long u64;

// 4 MB transposed+padded W_lin: g_wlinT[k][a] = W_lin[a][k], a padded 100->128 with zeros
__device__ float g_wlinT[8192 * 128];

__global__ void __launch_bounds__(256)
transpose_wlin_kernel(const float* __restrict__ W_lin) {
    int idx = blockIdx.x * 256 + threadIdx.x;   // 0 .. 8192*128-1
    int a = idx & 127;
    int k = idx >> 7;
    g_wlinT[idx] = (a < 100) ? W_lin[a * 8192 + k] : 0.0f;
}

static __device__ __forceinline__ float sigf(float v) {
    return __fdividef(1.0f, 1.0f + __expf(-v));
}
static __device__ __forceinline__ float tanh_acc(float v) {
    return 1.0f - __fdividef(2.0f, __expf(2.0f * v) + 1.0f);
}
static __device__ __forceinline__ u64 pack2(float s) {
    u64 r; asm("mov.b64 %0, {%1, %1};" : "=l"(r) : "f"(s)); return r;
}
static __device__ __forceinline__ u64 pack2f(float a, float b) {
    u64 r; asm("mov.b64 %0, {%1, %2};" : "=l"(r) : "f"(a), "f"(b)); return r;
}
static __device__ __forceinline__ float2 unpk(u64 v) {
    float2 f; asm("mov.b64 {%0, %1}, %2;" : "=f"(f.x), "=f"(f.y) : "l"(v)); return f;
}
static __device__ __forceinline__ void fma2(u64 &d, u64 w, u64 s) {
    asm("fma.rn.f32x2 %0, %1, %2, %0;" : "+l"(d) : "l"(w), "l"(s));
}
static __device__ __forceinline__ void cp16(uint32_t dst, const void* src) {
    asm volatile("cp.async.cg.shared.global [%0], [%1], 16;" :: "r"(dst), "l"(src));
}

__global__ void __launch_bounds__(NTH, 1)
lstm_fused_kernel(const float* __restrict__ x,      // [8192,128,32]
                  const float* __restrict__ W_ih,   // [256,32]
                  const float* __restrict__ W_hh,   // [256,64]
                  const float* __restrict__ b_ih,   // [256]
                  const float* __restrict__ b_hh,   // [256]
                  const float* __restrict__ b_lin,  // [100]
                  float* __restrict__ out)          // [8192,100]
{
    constexpr int T = 128, F = 32, H = 64;
    extern __shared__ float smem[];
    float4* s_wih  = (float4*)smem;              // [F][2][32]   : 2048 float4
    float4* s_whh  = (float4*)(smem + 8192);     // [H][2][32]   : 4096 float4
    float4* s_bias = (float4*)(smem + 24576);    // [2][32]      : 64 float4
    float*  s_wlin = smem + 24832;               // [64][WLS=128]: 8192 floats

    const int tid  = threadIdx.x;
    const int lane = tid & 31;
    const int warp = tid >> 5;

    // ---- one-time staging: permuted weights so gate g = lane + 32*(4m+c) ----
    for (int u = tid; u < F * 64; u += NTH) {
        int f = u >> 6, m = (u >> 5) & 1, l = u & 31;
        float4 v;
        v.x = W_ih[(l + 32 * (4 * m + 0)) * F + f];
        v.y = W_ih[(l + 32 * (4 * m + 1)) * F + f];
        v.z = W_ih[(l + 32 * (4 * m + 2)) * F + f];
        v.w = W_ih[(l + 32 * (4 * m + 3)) * F + f];
        s_wih[u] = v;
    }
    for (int u = tid; u < H * 64; u += NTH) {
        int j = u >> 6, m = (u >> 5) & 1, l = u & 31;
        float4 v;
        v.x = W_hh[(l + 32 * (4 * m + 0)) * H + j];
        v.y = W_hh[(l + 32 * (4 * m + 1)) * H + j];
        v.z = W_hh[(l + 32 * (4 * m + 2)) * H + j];
        v.w = W_hh[(l + 32 * (4 * m + 3)) * H + j];
        s_whh[u] = v;
    }
    if (tid < 64) {
        int m = (tid >> 5) & 1, l = tid & 31;
        float4 v;
        v.x = b_ih[l + 32 * (4 * m + 0)] + b_hh[l + 32 * (4 * m + 0)];
        v.y = b_ih[l + 32 * (4 * m + 1)] + b_hh[l + 32 * (4 * m + 1)];
        v.z = b_ih[l + 32 * (4 * m + 2)] + b_hh[l + 32 * (4 * m + 2)];
        v.w = b_ih[l + 32 * (4 * m + 3)] + b_hh[l + 32 * (4 * m + 3)];
        s_bias[tid] = v;
    }

    // R rows per warp, 64 rows per block, grid 128 => single wave
    const int row0 = blockIdx.x * (8 * R) + warp * R;

    float h_lo[R], h_hi[R], c_lo[R], c_hi[R], xv[R], xn[R];
    u64 lgA[R], lgB[R];

    u64 blA = 0, blB = 0;
    if (lane < 25) {
        float4 b = *(const float4*)(b_lin + 4 * lane);
        blA = pack2f(b.x, b.y);
        blB = pack2f(b.z, b.w);
    }
    const float* xb = x + (size_t)row0 * T * F + lane;
    #pragma unroll
    for (int r = 0; r < R; ++r) {
        h_lo[r] = h_hi[r] = c_lo[r] = c_hi[r] = 0.f;
        lgA[r] = blA; lgB[r] = blB;
        xn[r] = xb[r * T * F];
    }

    const uint32_t wlin_smem = (uint32_t)__cvta_generic_to_shared(s_wlin);

    __syncthreads();

    for (int t = 0; t < T; ++t) {
        // issue staging of this step's W_lin slice: linear 32KB copy (8x 16B/thread)
        {
            const char* src = (const char*)(g_wlinT + t * 8192) + tid * 16;
            uint32_t dst = wlin_smem + tid * 16;
            #pragma unroll
            for (int k = 0; k < 8; ++k)
                cp16(dst + k * 4096, src + k * 4096);
            asm volatile("cp.async.commit_group;" ::: "memory");
        }

        #pragma unroll
        for (int r = 0; r < R; ++r) xv[r] = xn[r];
        int tn = (t + 1 < T) ? (t + 1) : t;
        #pragma unroll
        for (int r = 0; r < R; ++r) xn[r] = xb[r * T * F + tn * F];

        // gate accumulators (packed pairs): A0=(i_lo,i_hi) A1=(f_lo,f_hi) B0=(g_lo,g_hi) B1=(o_lo,o_hi)
        u64 aA0[R], aA1[R], aB0[R], aB1[R];
        {
            ulonglong2 bb0 = ((const ulonglong2*)s_bias)[lane];
            ulonglong2 bb1 = ((const ulonglong2*)s_bias)[32 + lane];
            #pragma unroll
            for (int r = 0; r < R; ++r) {
                aA0[r] = bb0.x; aA1[r] = bb0.y;
                aB0[r] = bb1.x; aB1[r] = bb1.y;
            }
        }

        #pragma unroll 4
        for (int f = 0; f < F; ++f) {
            ulonglong2 w0 = *(const ulonglong2*)(s_wih + f * 64 + lane);
            ulonglong2 w1 = *(const ulonglong2*)(s_wih + f * 64 + 32 + lane);
            #pragma unroll
            for (int r = 0; r < R; ++r) {
                u64 s2 = pack2(__shfl_sync(0xffffffffu, xv[r], f));
                fma2(aA0[r], w0.x, s2); fma2(aA1[r], w0.y, s2);
                fma2(aB0[r], w1.x, s2); fma2(aB1[r], w1.y, s2);
            }
        }
        #pragma unroll 2
        for (int j = 0; j < 32; ++j) {
            ulonglong2 w0 = *(const ulonglong2*)(s_whh + j * 64 + lane);
            ulonglong2 w1 = *(const ulonglong2*)(s_whh + j * 64 + 32 + lane);
            ulonglong2 W0 = *(const ulonglong2*)(s_whh + (j + 32) * 64 + lane);
            ulonglong2 W1 = *(const ulonglong2*)(s_whh + (j + 32) * 64 + 32 + lane);
            #pragma unroll
            for (int r = 0; r < R; ++r) {
                u64 s2 = pack2(__shfl_sync(0xffffffffu, h_lo[r], j));
                fma2(aA0[r], w0.x, s2); fma2(aA1[r], w0.y, s2);
                fma2(aB0[r], w1.x, s2); fma2(aB1[r], w1.y, s2);
                u64 u2 = pack2(__shfl_sync(0xffffffffu, h_hi[r], j));
                fma2(aA0[r], W0.x, u2); fma2(aA1[r], W0.y, u2);
                fma2(aB0[r], W1.x, u2); fma2(aB1[r], W1.y, u2);
            }
        }

        // elementwise LSTM update
        #pragma unroll
        for (int r = 0; r < R; ++r) {
            float2 iv = unpk(aA0[r]);
            float2 fv = unpk(aA1[r]);
            float2 gv = unpk(aB0[r]);
            float2 ov = unpk(aB1[r]);
            c_lo[r] = sigf(fv.x) * c_lo[r] + sigf(iv.x) * tanh_acc(gv.x);
            c_hi[r] = sigf(fv.y) * c_hi[r] + sigf(iv.y) * tanh_acc(gv.y);
            h_lo[r] = sigf(ov.x) * tanh_acc(c_lo[r]);
            h_hi[r] = sigf(ov.y) * tanh_acc(c_hi[r]);
        }

        asm volatile("cp.async.wait_group 0;" ::: "memory");
        __syncthreads();  // s_wlin staged

        // online logits accumulation: lg[a] += h_t[j] * W_lin[a, t*64+j]
        #pragma unroll 2
        for (int j = 0; j < 32; ++j) {
            ulonglong2 wl = *(const ulonglong2*)(s_wlin + j * WLS + 4 * lane);
            ulonglong2 wh = *(const ulonglong2*)(s_wlin + (j + 32) * WLS + 4 * lane);
            #pragma unroll
            for (int r = 0; r < R; ++r) {
                u64 v2 = pack2(__shfl_sync(0xffffffffu, h_lo[r], j));
                fma2(lgA[r], wl.x, v2); fma2(lgB[r], wl.y, v2);
                u64 u2 = pack2(__shfl_sync(0xffffffffu, h_hi[r], j));
                fma2(lgA[r], wh.x, u2); fma2(lgB[r], wh.y, u2);
            }
        }

        __syncthreads();  // protect s_wlin before next overwrite
    }

    // ---- softmax over 100 assets, 4 per lane in lanes 0..24 ----
    const float NEG_INF = __int_as_float(0xff800000);
    #pragma unroll
    for (int r = 0; r < R; ++r) {
        float2 pa = unpk(lgA[r]);
        float2 pb = unpk(lgB[r]);
        float m = (lane < 25) ? fmaxf(fmaxf(pa.x, pa.y), fmaxf(pb.x, pb.y)) : NEG_INF;
        #pragma unroll
        for (int off = 16; off; off >>= 1)
            m = fmaxf(m, __shfl_xor_sync(0xffffffffu, m, off));
        float e0 = 0.f, e1 = 0.f, e2 = 0.f, e3 = 0.f, s = 0.f;
        if (lane < 25) {
            e0 = __expf(pa.x - m); e1 = __expf(pa.y - m);
            e2 = __expf(pb.x - m); e3 = __expf(pb.y - m);
            s = (e0 + e1) + (e2 + e3);
        }
        #pragma unroll
        for (int off = 16; off; off >>= 1)
            s += __shfl_xor_sync(0xffffffffu, s, off);
        if (lane < 25) {
            float inv = __fdividef(1.0f, s);
            float4 o = make_float4(e0 * inv, e1 * inv, e2 * inv, e3 * inv);
            *(float4*)(out + (size_t)(row0 + r) * 100 + 4 * lane) = o;
        }
    }
}

extern "C" void kernel_launch(void* const* d_in, const int* in_sizes, int n_in,
                              void* d_out, int out_size) {
    const float* x     = (const float*)d_in[0];
    const float* W_ih  = (const float*)d_in[1];
    const float* W_hh  = (const float*)d_in[2];
    const float* b_ih  = (const float*)d_in[3];
    const float* b_hh  = (const float*)d_in[4];
    const float* W_lin = (const float*)d_in[5];
    const float* b_lin = (const float*)d_in[6];
    float* out = (float*)d_out;

    transpose_wlin_kernel<<<8192 * 128 / 256, 256>>>(W_lin);

    const int smem_bytes = (24832 + 64 * WLS) * 4;  // 132096
    cudaFuncSetAttribute(lstm_fused_kernel,
                         cudaFuncAttributeMaxDynamicSharedMemorySize, smem_bytes);
    lstm_fused_kernel<<<128, NTH, smem_bytes>>>(x, W_ih, W_hh, b_ih, b_hh,
                                                b_lin, out);
}

// round 11
// speedup vs baseline: 1.7160x; 1.0009x over previous
#include <cuda_runtime.h>
#include <cstdint>

#define NTH 256
#define WLS 128
#define R 8
typedef unsigned long long u64;

// 4 MB transposed+padded W_lin: g_wlinT[k][a] = W_lin[a][k], a padded 100->128 with zeros
__device__ float g_wlinT[8192 * 128];

__global__ void __launch_bounds__(256)
transpose_wlin_kernel(const float* __restrict__ W_lin) {
    int idx = blockIdx.x * 256 + threadIdx.x;   // 0 .. 8192*128-1
    int a = idx & 127;
    int k = idx >> 7;
    g_wlinT[idx] = (a < 100) ? W_lin[a * 8192 + k] : 0.0f;
}

static __device__ __forceinline__ float sigf(float v) {
    return __fdividef(1.0f, 1.0f + __expf(-v));
}
static __device__ __forceinline__ float tanh_acc(float v) {
    return 1.0f - __fdividef(2.0f, __expf(2.0f * v) + 1.0f);
}
static __device__ __forceinline__ u64 pack2(float s) {
    u64 r; asm("mov.b64 %0, {%1, %1};" : "=l"(r) : "f"(s)); return r;
}
static __device__ __forceinline__ u64 pack2f(float a, float b) {
    u64 r; asm("mov.b64 %0, {%1, %2};" : "=l"(r) : "f"(a), "f"(b)); return r;
}
static __device__ __forceinline__ float2 unpk(u64 v) {
    float2 f; asm("mov.b64 {%0, %1}, %2;" : "=f"(f.x), "=f"(f.y) : "l"(v)); return f;
}
static __device__ __forceinline__ void fma2(u64 &d, u64 w, u64 s) {
    asm("fma.rn.f32x2 %0, %1, %2, %0;" : "+l"(d) : "l"(w), "l"(s));
}
static __device__ __forceinline__ void cp16(uint32_t dst, const void* src) {
    asm volatile("cp.async.cg.shared.global [%0], [%1], 16;" :: "r"(dst), "l"(src));
}

__global__ void __launch_bounds__(NTH, 1)
lstm_fused_kernel(const float* __restrict__ x,      // [8192,128,32]
                  const float* __restrict__ W_ih,   // [256,32]
                  const float* __restrict__ W_hh,   // [256,64]
                  const float* __restrict__ b_ih,   // [256]
                  const float* __restrict__ b_hh,   // [256]
                  const float* __restrict__ b_lin,  // [100]
                  float* __restrict__ out)          // [8192,100]
{
    constexpr int T = 128, F = 32, H = 64;
    extern __shared__ float smem[];
    float4* s_wih  = (float4*)smem;              // [F][2][32]   : 2048 float4
    float4* s_whh  = (float4*)(smem + 8192);     // [H][2][32]   : 4096 float4
    float4* s_bias = (float4*)(smem + 24576);    // [2][32]      : 64 float4
    float*  s_wlin = smem + 24832;               // [64][WLS=128]: 8192 floats

    const int tid  = threadIdx.x;
    const int lane = tid & 31;
    const int warp = tid >> 5;

    // ---- one-time staging: permuted weights so gate g = lane + 32*(4m+c) ----
    for (int u = tid; u < F * 64; u += NTH) {
        int f = u >> 6, m = (u >> 5) & 1, l = u & 31;
        float4 v;
        v.x = W_ih[(l + 32 * (4 * m + 0)) * F + f];
        v.y = W_ih[(l + 32 * (4 * m + 1)) * F + f];
        v.z = W_ih[(l + 32 * (4 * m + 2)) * F + f];
        v.w = W_ih[(l + 32 * (4 * m + 3)) * F + f];
        s_wih[u] = v;
    }
    for (int u = tid; u < H * 64; u += NTH) {
        int j = u >> 6, m = (u >> 5) & 1, l = u & 31;
        float4 v;
        v.x = W_hh[(l + 32 * (4 * m + 0)) * H + j];
        v.y = W_hh[(l + 32 * (4 * m + 1)) * H + j];
        v.z = W_hh[(l + 32 * (4 * m + 2)) * H + j];
        v.w = W_hh[(l + 32 * (4 * m + 3)) * H + j];
        s_whh[u] = v;
    }
    if (tid < 64) {
        int m = (tid >> 5) & 1, l = tid & 31;
        float4 v;
        v.x = b_ih[l + 32 * (4 * m + 0)] + b_hh[l + 32 * (4 * m + 0)];
        v.y = b_ih[l + 32 * (4 * m + 1)] + b_hh[l + 32 * (4 * m + 1)];
        v.z = b_ih[l + 32 * (4 * m + 2)] + b_hh[l + 32 * (4 * m + 2)];
        v.w = b_ih[l + 32 * (4 * m + 3)] + b_hh[l + 32 * (4 * m + 3)];
        s_bias[tid] = v;
    }

    // R rows per warp, 64 rows per block, grid 128 => single wave
    const int row0 = blockIdx.x * (8 * R) + warp * R;

    float h_lo[R], h_hi[R], c_lo[R], c_hi[R], xv[R], xn[R];
    u64 lgA[R], lgB[R];

    u64 blA = 0, blB = 0;
    if (lane < 25) {
        float4 b = *(const float4*)(b_lin + 4 * lane);
        blA = pack2f(b.x, b.y);
        blB = pack2f(b.z, b.w);
    }
    const float* xb = x + (size_t)row0 * T * F + lane;
    #pragma unroll
    for (int r = 0; r < R; ++r) {
        h_lo[r] = h_hi[r] = c_lo[r] = c_hi[r] = 0.f;
        lgA[r] = blA; lgB[r] = blB;
        xn[r] = xb[r * T * F];
    }

    const uint32_t wlin_smem = (uint32_t)__cvta_generic_to_shared(s_wlin);

    __syncthreads();

    for (int t = 0; t < T; ++t) {
        // issue staging of this step's W_lin slice: linear 32KB copy (8x 16B/thread)
        {
            const char* src = (const char*)(g_wlinT + t * 8192) + tid * 16;
            uint32_t dst = wlin_smem + tid * 16;
            #pragma unroll
            for (int k = 0; k < 8; ++k)
                cp16(dst + k * 4096, src + k * 4096);
            asm volatile("cp.async.commit_group;" ::: "memory");
        }

        #pragma unroll
        for (int r = 0; r < R; ++r) xv[r] = xn[r];
        int tn = (t + 1 < T) ? (t + 1) : t;
        #pragma unroll
        for (int r = 0; r < R; ++r) xn[r] = xb[r * T * F + tn * F];

        // gate accumulators (packed pairs): A0=(i_lo,i_hi) A1=(f_lo,f_hi) B0=(g_lo,g_hi) B1=(o_lo,o_hi)
        u64 aA0[R], aA1[R], aB0[R], aB1[R];
        {
            ulonglong2 bb0 = ((const ulonglong2*)s_bias)[lane];
            ulonglong2 bb1 = ((const ulonglong2*)s_bias)[32 + lane];
            #pragma unroll
            for (int r = 0; r < R; ++r) {
                aA0[r] = bb0.x; aA1[r] = bb0.y;
                aB0[r] = bb1.x; aB1[r] = bb1.y;
            }
        }

        #pragma unroll 4
        for (int f = 0; f < F; ++f) {
            ulonglong2 w0 = *(const ulonglong2*)(s_wih + f * 64 + lane);
            ulonglong2 w1 = *(const ulonglong2*)(s_wih + f * 64 + 32 + lane);
            #pragma unroll
            for (int r = 0; r < R; ++r) {
                u64 s2 = pack2(__shfl_sync(0xffffffffu, xv[r], f));
                fma2(aA0[r], w0.x, s2); fma2(aA1[r], w0.y, s2);
                fma2(aB0[r], w1.x, s2); fma2(aB1[r], w1.y, s2);
            }
        }
        #pragma unroll 2
        for (int j = 0; j < 32; ++j) {
            ulonglong2 w0 = *(const ulonglong2*)(s_whh + j * 64 + lane);
            ulonglong2 w1 = *(const ulonglong2*)(s_whh + j * 64 + 32 + lane);
            ulonglong2 W0 = *(const ulonglong2*)(s_whh + (j + 32) * 64 + lane);
            ulonglong2 W1 = *(const ulonglong2*)(s_whh + (j + 32) * 64 + 32 + lane);
            #pragma unroll
            for (int r = 0; r < R; ++r) {
                u64 s2 = pack2(__shfl_sync(0xffffffffu, h_lo[r], j));
                fma2(aA0[r], w0.x, s2); fma2(aA1[r], w0.y, s2);
                fma2(aB0[r], w1.x, s2); fma2(aB1[r], w1.y, s2);
                u64 u2 = pack2(__shfl_sync(0xffffffffu, h_hi[r], j));
                fma2(aA0[r], W0.x, u2); fma2(aA1[r], W0.y, u2);
                fma2(aB0[r], W1.x, u2); fma2(aB1[r], W1.y, u2);
            }
        }

        // elementwise LSTM update
        #pragma unroll
        for (int r = 0; r < R; ++r) {
            float2 iv = unpk(aA0[r]);
            float2 fv = unpk(aA1[r]);
            float2 gv = unpk(aB0[r]);
            float2 ov = unpk(aB1[r]);
            c_lo[r] = sigf(fv.x) * c_lo[r] + sigf(iv.x) * tanh_acc(gv.x);
            c_hi[r] = sigf(fv.y) * c_hi[r] + sigf(iv.y) * tanh_acc(gv.y);
            h_lo[r] = sigf(ov.x) * tanh_acc(c_lo[r]);
            h_hi[r] = sigf(ov.y) * tanh_acc(c_hi[r]);
        }

        asm volatile("cp.async.wait_group 0;" ::: "memory");
        __syncthreads();  // s_wlin staged

        // online logits accumulation: lg[a] += h_t[j] * W_lin[a, t*64+j]
        #pragma unroll 2
        for (int j = 0; j < 32; ++j) {
            ulonglong2 wl = *(const ulonglong2*)(s_wlin + j * WLS + 4 * lane);
            ulonglong2 wh = *(const ulonglong2*)(s_wlin + (j + 32) * WLS + 4 * lane);
            #pragma unroll
            for (int r = 0; r < R; ++r) {
                u64 v2 = pack2(__shfl_sync(0xffffffffu, h_lo[r], j));
                fma2(lgA[r], wl.x, v2); fma2(lgB[r], wl.y, v2);
                u64 u2 = pack2(__shfl_sync(0xffffffffu, h_hi[r], j));
                fma2(lgA[r], wh.x, u2); fma2(lgB[r], wh.y, u2);
            }
        }

        __syncthreads();  // protect s_wlin before next overwrite
    }

    // ---- softmax over 100 assets, 4 per lane in lanes 0..24 ----
    const float NEG_INF = __int_as_float(0xff800000);
    #pragma unroll
    for (int r = 0; r < R; ++r) {
        float2 pa = unpk(lgA[r]);
        float2 pb = unpk(lgB[r]);
        float m = (lane < 25) ? fmaxf(fmaxf(pa.x, pa.y), fmaxf(pb.x, pb.y)) : NEG_INF;
        #pragma unroll
        for (int off = 16; off; off >>= 1)
            m = fmaxf(m, __shfl_xor_sync(0xffffffffu, m, off));
        float e0 = 0.f, e1 = 0.f, e2 = 0.f, e3 = 0.f, s = 0.f;
        if (lane < 25) {
            e0 = __expf(pa.x - m); e1 = __expf(pa.y - m);
            e2 = __expf(pb.x - m); e3 = __expf(pb.y - m);
            s = (e0 + e1) + (e2 + e3);
        }
        #pragma unroll
        for (int off = 16; off; off >>= 1)
            s += __shfl_xor_sync(0xffffffffu, s, off);
        if (lane < 25) {
            float inv = __fdividef(1.0f, s);
            float4 o = make_float4(e0 * inv, e1 * inv, e2 * inv, e3 * inv);
            *(float4*)(out + (size_t)(row0 + r) * 100 + 4 * lane) = o;
        }
    }
}

extern "C" void kernel_launch(void* const* d_in, const int* in_sizes, int n_in,
                              void* d_out, int out_size) {
    const float* x     = (const float*)d_in[0];
    const float* W_ih  = (const float*)d_in[1];
    const float* W_hh  = (const float*)d_in[2];
    const float* b_ih  = (const float*)d_in[3];
    const float* b_hh  = (const float*)d_in[4];
    const float* W_lin = (const float*)d_in[5];
    const float* b_lin = (const float*)d_in[6];
    float* out = (float*)d_out;

    transpose_wlin_kernel<<<8192 * 128 / 256, 256>>>(W_lin);

    const int smem_bytes = (24832 + 64 * WLS) * 4;  // 132096
    cudaFuncSetAttribute(lstm_fused_kernel,
                         cudaFuncAttributeMaxDynamicSharedMemorySize, smem_bytes);
    lstm_fused_kernel<<<128, NTH, smem_bytes>>>(x, W_ih, W_hh, b_ih, b_hh,
                                                b_lin, out);
}